// round 11
// baseline (speedup 1.0000x reference)
#include <cuda_runtime.h>

// SphKernel: out[b,v,p,n,c] = g_n(r) * Y_c(rotate(frame, normalize(patch)))
// B=4, V=4096, P=64, NR=3, C=16. 1,048,576 points; 48 f32 out/point (201 MB).
//
// R11 = exact R4 structure (best wall 33.28us: 128tpb, 16 blocks/SM,
// block-wide staging, coalesced float4 write-out) with store policy switched
// __stcs -> __stwt (write-through). Established across R3-R10: store policy
// is the ONLY variable moving wall time (streaming 33.3-33.5, write-back
// 38.8-39.1); .cs still allocates+evicts L2 lines on the drain path; .wt
// skips the allocation cycle entirely. Single-variable probe.

#define TPB 128
#define PT_F4 5                      // float4 chunks per point
#define PT_STRIDE 20                 // floats per point row
#define VEC4_PER_BLOCK (TPB * 12)    // 1536 float4 per block

__global__ __launch_bounds__(TPB, 16)
void sph_kernel(const float* __restrict__ patches,
                const float* __restrict__ frames,
                const float* __restrict__ r,
                float* __restrict__ out)
{
    __shared__ float4 sh4[TPB * PT_F4];           // 10240 B
    float* sh = reinterpret_cast<float*>(sh4);

    const int tid = threadIdx.x;
    const int pt  = blockIdx.x * TPB + tid;       // global point index
    const int fi  = pt >> 6;                      // frame index (P = 64)

    // ---- load & normalize direction ----
    const float px = __ldg(patches + 3 * pt + 0);
    const float py = __ldg(patches + 3 * pt + 1);
    const float pz = __ldg(patches + 3 * pt + 2);
    const float sq  = px * px + py * py + pz * pz;
    const float inv = rsqrtf(fmaxf(sq, 1e-12f));
    const float dx = px * inv, dy = py * inv, dz = pz * inv;

    // ---- rotate into local frame: proj_j = sum_i F[i][j] * d_i ----
    const float* F = frames + 9 * fi;             // warp-uniform -> broadcast
    const float x = __ldg(F + 0) * dx + __ldg(F + 3) * dy + __ldg(F + 6) * dz;
    const float y = __ldg(F + 1) * dx + __ldg(F + 4) * dy + __ldg(F + 7) * dz;
    const float z = __ldg(F + 2) * dx + __ldg(F + 5) * dy + __ldg(F + 8) * dz;

    // ---- spherical harmonics (reference channel order) ----
    const float x2 = x * x, y2 = y * y, z2 = z * z;
    const float xy = x * y, yz = y * z, zx = z * x;

    float4* row4 = sh4 + tid * PT_F4;
    row4[0] = make_float4(
        0.28209479177387814f,                                   // Y00
        0.4886025119029199f * z,                                // Y10
        0.31539156525252005f * (2.f * z2 - x2 - y2),            // Y20
        0.3731763325901154f * z * (2.f * z2 - 3.f * x2 - 3.f * y2)); // Y30
    row4[1] = make_float4(
        0.4886025119029199f * x,                                // Y1_10
        0.4886025119029199f * y,                                // Y1_11
        1.0925484305920792f * zx,                               // Y2_10
        1.0925484305920792f * yz);                              // Y2_11
    row4[2] = make_float4(
        0.4570457994644658f * x * (4.f * z2 - x2 - y2),         // Y3_10
        0.4570457994644658f * y * (4.f * z2 - x2 - y2),         // Y3_11
        0.5462742152960396f * (x2 - y2),                        // Y2_20
        1.0925484305920792f * xy);                              // Y2_21
    row4[3] = make_float4(
        1.4453057213202771f * z * (x2 - y2),                    // Y3_20
        2.8906114426405543f * xy * z,                           // Y3_21
        0.5900435899266435f * x * (x2 - 3.f * y2),              // Y3_30
        0.5900435899266435f * y * (3.f * x2 - y2));             // Y3_31

    // ---- gaussian shells: centers {0, 0.5, 1}, normalized ----
    const float rv = __ldg(r + pt);
    const float K = -2.772588722239781f;          // 4 * ln(0.5)
    const float d1 = rv - 0.5f, d2 = rv - 1.0f;
    const float g0 = __expf(K * rv * rv);
    const float g1 = __expf(K * d1 * d1);
    const float g2 = __expf(K * d2 * d2);
    const float ginv = __fdividef(1.0f, g0 + g1 + g2);
    row4[4] = make_float4(g0 * ginv, g1 * ginv, g2 * ginv, 0.0f);

    __syncthreads();

    // ---- coalesced write-through float4 write-out ----
    float4* out4 = reinterpret_cast<float4*>(out);
    const size_t base = (size_t)blockIdx.x * VEC4_PER_BLOCK;
#pragma unroll
    for (int k = 0; k < 12; k++) {
        const int f4 = k * TPB + tid;       // float4 index within block tile
        const int p  = f4 / 12;             // point within block
        const int r4 = f4 - p * 12;
        const int shell = r4 >> 2;          // 0..2
        const int cg    = r4 & 3;           // Y quad 0..3
        const float4 Yv = sh4[p * PT_F4 + cg];            // LDS.128
        const float g   = sh[p * PT_STRIDE + 16 + shell]; // LDS.32 (broadcasty)
        __stwt(out4 + base + f4,
               make_float4(g * Yv.x, g * Yv.y, g * Yv.z, g * Yv.w));
    }
}

extern "C" void kernel_launch(void* const* d_in, const int* in_sizes, int n_in,
                              void* d_out, int out_size)
{
    const float* patches = (const float*)d_in[0];  // [4,4096,64,3]
    const float* frames  = (const float*)d_in[1];  // [4,4096,3,3]
    const float* r       = (const float*)d_in[2];  // [4,4096,64]
    float* out = (float*)d_out;                    // [4,4096,64,3,16]

    const int total_points = in_sizes[2];          // 1,048,576
    const int blocks = total_points / TPB;         // 8192

    sph_kernel<<<blocks, TPB>>>(patches, frames, r, out);
}

// round 12
// speedup vs baseline: 1.1672x; 1.1672x over previous
#include <cuda_runtime.h>
#include <cstdint>

// SphKernel: out[b,v,p,n,c] = g_n(r) * Y_c(rotate(frame, normalize(patch)))
// B=4, V=4096, P=64, NR=3, C=16. 1,048,576 points; 48 f32 out/point (201 MB).
//
// R12: TMA bulk-store drain. Established R3-R11: wall time is purely a
// function of the store drain path (.cs 33.3us | wb/.wt ~39us); per-lane STG
// structure is irrelevant. This round swaps the requestor: each block writes
// its 48*128 outputs into a packed final-layout smem buffer, then ONE
// cp.async.bulk (24576 B linear burst, L2::evict_first hint) drains it via
// the TMA engine. wait_group.read lets the block retire as soon as smem is
// consumed; the drain continues behind it.

#define TPB 128
#define BLOCK_BYTES (TPB * 48 * 4)    // 24576

__global__ __launch_bounds__(TPB, 9)
void sph_kernel(const float* __restrict__ patches,
                const float* __restrict__ frames,
                const float* __restrict__ r,
                float* __restrict__ out)
{
    __shared__ __align__(128) float4 buf[TPB * 12];   // 24576 B, packed final layout

    const int tid = threadIdx.x;
    const int pt  = blockIdx.x * TPB + tid;           // global point index
    const int fi  = pt >> 6;                          // frame index (P = 64)

    // ---- load & normalize direction ----
    const float px = __ldg(patches + 3 * pt + 0);
    const float py = __ldg(patches + 3 * pt + 1);
    const float pz = __ldg(patches + 3 * pt + 2);
    const float sq  = px * px + py * py + pz * pz;
    const float inv = rsqrtf(fmaxf(sq, 1e-12f));
    const float dx = px * inv, dy = py * inv, dz = pz * inv;

    // ---- rotate into local frame: proj_j = sum_i F[i][j] * d_i ----
    const float* F = frames + 9 * fi;                 // warp-uniform -> broadcast
    const float x = __ldg(F + 0) * dx + __ldg(F + 3) * dy + __ldg(F + 6) * dz;
    const float y = __ldg(F + 1) * dx + __ldg(F + 4) * dy + __ldg(F + 7) * dz;
    const float z = __ldg(F + 2) * dx + __ldg(F + 5) * dy + __ldg(F + 8) * dz;

    // ---- spherical harmonics (reference channel order), held as 4 quads ----
    const float x2 = x * x, y2 = y * y, z2 = z * z;
    const float xy = x * y, yz = y * z, zx = z * x;

    const float4 Y0 = make_float4(
        0.28209479177387814f,                                   // Y00
        0.4886025119029199f * z,                                // Y10
        0.31539156525252005f * (2.f * z2 - x2 - y2),            // Y20
        0.3731763325901154f * z * (2.f * z2 - 3.f * x2 - 3.f * y2)); // Y30
    const float4 Y1 = make_float4(
        0.4886025119029199f * x,                                // Y1_10
        0.4886025119029199f * y,                                // Y1_11
        1.0925484305920792f * zx,                               // Y2_10
        1.0925484305920792f * yz);                              // Y2_11
    const float4 Y2 = make_float4(
        0.4570457994644658f * x * (4.f * z2 - x2 - y2),         // Y3_10
        0.4570457994644658f * y * (4.f * z2 - x2 - y2),         // Y3_11
        0.5462742152960396f * (x2 - y2),                        // Y2_20
        1.0925484305920792f * xy);                              // Y2_21
    const float4 Y3 = make_float4(
        1.4453057213202771f * z * (x2 - y2),                    // Y3_20
        2.8906114426405543f * xy * z,                           // Y3_21
        0.5900435899266435f * x * (x2 - 3.f * y2),              // Y3_30
        0.5900435899266435f * y * (3.f * x2 - y2));             // Y3_31

    // ---- gaussian shells: centers {0, 0.5, 1}, normalized ----
    const float rv = __ldg(r + pt);
    const float K = -2.772588722239781f;              // 4 * ln(0.5)
    const float d1 = rv - 0.5f, d2 = rv - 1.0f;
    const float e0 = __expf(K * rv * rv);
    const float e1 = __expf(K * d1 * d1);
    const float e2 = __expf(K * d2 * d2);
    const float ginv = __fdividef(1.0f, e0 + e1 + e2);
    const float g0 = e0 * ginv, g1 = e1 * ginv, g2 = e2 * ginv;

    // ---- write 48 products directly into packed final layout ----
    float4* row = buf + tid * 12;
    row[0]  = make_float4(g0 * Y0.x, g0 * Y0.y, g0 * Y0.z, g0 * Y0.w);
    row[1]  = make_float4(g0 * Y1.x, g0 * Y1.y, g0 * Y1.z, g0 * Y1.w);
    row[2]  = make_float4(g0 * Y2.x, g0 * Y2.y, g0 * Y2.z, g0 * Y2.w);
    row[3]  = make_float4(g0 * Y3.x, g0 * Y3.y, g0 * Y3.z, g0 * Y3.w);
    row[4]  = make_float4(g1 * Y0.x, g1 * Y0.y, g1 * Y0.z, g1 * Y0.w);
    row[5]  = make_float4(g1 * Y1.x, g1 * Y1.y, g1 * Y1.z, g1 * Y1.w);
    row[6]  = make_float4(g1 * Y2.x, g1 * Y2.y, g1 * Y2.z, g1 * Y2.w);
    row[7]  = make_float4(g1 * Y3.x, g1 * Y3.y, g1 * Y3.z, g1 * Y3.w);
    row[8]  = make_float4(g2 * Y0.x, g2 * Y0.y, g2 * Y0.z, g2 * Y0.w);
    row[9]  = make_float4(g2 * Y1.x, g2 * Y1.y, g2 * Y1.z, g2 * Y1.w);
    row[10] = make_float4(g2 * Y2.x, g2 * Y2.y, g2 * Y2.z, g2 * Y2.w);
    row[11] = make_float4(g2 * Y3.x, g2 * Y3.y, g2 * Y3.z, g2 * Y3.w);

    __syncthreads();

    // ---- single TMA bulk store: smem -> gmem, evict-first, exit on read-done ----
    if (tid == 0) {
        asm volatile("fence.proxy.async.shared::cta;" ::: "memory");
        uint32_t saddr;
        asm("{ .reg .u64 t; cvta.to.shared.u64 t, %1; cvt.u32.u64 %0, t; }"
            : "=r"(saddr) : "l"(buf));
        const uint64_t gaddr =
            (uint64_t)out + (uint64_t)blockIdx.x * BLOCK_BYTES;
        asm volatile(
            "{\n\t"
            ".reg .b64 pol;\n\t"
            "createpolicy.fractional.L2::evict_first.b64 pol, 1.0;\n\t"
            "cp.async.bulk.global.shared::cta.bulk_group.L2::cache_hint "
            "[%0], [%1], %2, pol;\n\t"
            "cp.async.bulk.commit_group;\n\t"
            "cp.async.bulk.wait_group.read 0;\n\t"
            "}"
            :: "l"(gaddr), "r"(saddr), "r"((int)BLOCK_BYTES)
            : "memory");
    }
}

extern "C" void kernel_launch(void* const* d_in, const int* in_sizes, int n_in,
                              void* d_out, int out_size)
{
    const float* patches = (const float*)d_in[0];  // [4,4096,64,3]
    const float* frames  = (const float*)d_in[1];  // [4,4096,3,3]
    const float* r       = (const float*)d_in[2];  // [4,4096,64]
    float* out = (float*)d_out;                    // [4,4096,64,3,16]

    const int total_points = in_sizes[2];          // 1,048,576
    const int blocks = total_points / TPB;         // 8192

    sph_kernel<<<blocks, TPB>>>(patches, frames, r, out);
}